// round 14
// baseline (speedup 1.0000x reference)
#include <cuda_runtime.h>
#include <cuda_fp16.h>
#include <math.h>
#include <stdint.h>

// Problem constants
#define TOK   32768          // B*N = 8*4096
#define NEXP  8
#define DDIM  512
#define BND   16777216       // TOK * DDIM
#define LN_EPS 1e-5f

// Fused GEMM config: BM=64 rows, BN=512 (full rows), BK=64, 512 threads
#define BM 64
#define BN 512
#define BK 64
#define NCHUNK (DDIM / BK)            // 8
#define ROWB 144                      // 64 fp16 = 128B + 16B pad
#define P1_B_OFF (BM * ROWB)          // 9216
#define P1_STAGE (P1_B_OFF + BN * ROWB) // 82944
#define A2_ROWB 1040                  // 512 fp16 = 1024B + 16B pad
#define A2_SIZE (BM * A2_ROWB)        // 66560
#define P2_BASE A2_SIZE               // phase2 B stages start here
#define P2_STAGE (BN * ROWB)          // 73728
#define SMEM_DYN (P2_BASE + 2 * P2_STAGE)  // 214016

// ---------------------------------------------------------------------------
// Scratch (__device__ globals; no allocations allowed)
// ---------------------------------------------------------------------------
__device__ int   g_cnt[NEXP];
__device__ int   g_pairTok[NEXP * TOK];
__device__ int   g_tokPair[TOK * 4];
__device__ float g_tokW[TOK * 4];
__device__ __half g_h2[(size_t)NEXP * TOK * DDIM];   // expert out (POST-LN2) fp16
__device__ float g_part[4096];
__device__ __half g_xh[(size_t)TOK * DDIM];          // x fp16 (token space)
__device__ __half g_w1t[(size_t)NEXP * DDIM * DDIM]; // W1^T fp16
__device__ __half g_w2t[(size_t)NEXP * DDIM * DDIM]; // W2^T fp16

// ---------------------------------------------------------------------------
// Helpers
// ---------------------------------------------------------------------------
__device__ __forceinline__ uint32_t smem_u32(const void* p) {
    uint32_t a;
    asm("{ .reg .u64 t; cvta.to.shared.u64 t, %1; cvt.u32.u64 %0, t; }" : "=r"(a) : "l"(p));
    return a;
}
__device__ __forceinline__ void cp16(uint32_t dst, const void* src) {
    asm volatile("cp.async.cg.shared.global [%0], [%1], 16;" :: "r"(dst), "l"(src));
}
#define CP_COMMIT() asm volatile("cp.async.commit_group;" ::: "memory")
#define CP_WAIT1()  asm volatile("cp.async.wait_group 1;" ::: "memory")
#define CP_WAIT0()  asm volatile("cp.async.wait_group 0;" ::: "memory")
__device__ __forceinline__ void ldsm4(uint32_t* r, uint32_t addr) {
    asm volatile("ldmatrix.sync.aligned.m8n8.x4.shared.b16 {%0,%1,%2,%3}, [%4];"
                 : "=r"(r[0]), "=r"(r[1]), "=r"(r[2]), "=r"(r[3]) : "r"(addr));
}
__device__ __forceinline__ void mma16816(float* c, const uint32_t* a, const uint32_t* b) {
    asm volatile(
        "mma.sync.aligned.m16n8k16.row.col.f32.f16.f16.f32 "
        "{%0,%1,%2,%3}, {%4,%5,%6,%7}, {%8,%9}, {%0,%1,%2,%3};"
        : "+f"(c[0]), "+f"(c[1]), "+f"(c[2]), "+f"(c[3])
        : "r"(a[0]), "r"(a[1]), "r"(a[2]), "r"(a[3]), "r"(b[0]), "r"(b[1]));
}

// ---------------------------------------------------------------------------
// 0) zero counters
// ---------------------------------------------------------------------------
__global__ void init_kernel() {
    if (threadIdx.x < NEXP) g_cnt[threadIdx.x] = 0;
}

// ---------------------------------------------------------------------------
// 1) gating: scores + routing + x fp16 round (token space)
// ---------------------------------------------------------------------------
__global__ void gating_kernel(const float* __restrict__ x,
                              const float* __restrict__ Wg,
                              const float* __restrict__ bg) {
    int gw = (blockIdx.x * blockDim.x + threadIdx.x) >> 5;
    if (gw >= TOK) return;
    int lane = threadIdx.x & 31;
    const float* xr = x + (size_t)gw * DDIM;
    __half* xh = g_xh + (size_t)gw * DDIM;

    float s[NEXP];
#pragma unroll
    for (int e = 0; e < NEXP; e++) s[e] = 0.f;
#pragma unroll
    for (int i = 0; i < 16; i++) {
        int d = lane + i * 32;
        float xv = xr[d];
        const float* wr = Wg + d * NEXP;
#pragma unroll
        for (int e = 0; e < NEXP; e++) s[e] += xv * wr[e];
        xh[d] = __float2half_rn(xv);
    }
#pragma unroll
    for (int e = 0; e < NEXP; e++) {
#pragma unroll
        for (int o = 16; o > 0; o >>= 1)
            s[e] += __shfl_xor_sync(0xffffffffu, s[e], o);
    }
    if (lane == 0) {
#pragma unroll
        for (int e = 0; e < NEXP; e++) s[e] += bg[e];
        int i0 = 0; float v0 = s[0];
        for (int e = 1; e < NEXP; e++) if (s[e] > v0) { v0 = s[e]; i0 = e; }
        int i1 = -1; float v1 = -1e30f;
        for (int e = 0; e < NEXP; e++) if (e != i0 && s[e] > v1) { v1 = s[e]; i1 = e; }
        int j0 = 0; float u0 = s[0];
        for (int e = 1; e < NEXP; e++) if (s[e] < u0) { u0 = s[e]; j0 = e; }
        int j1 = -1; float u1 = 1e30f;
        for (int e = 0; e < NEXP; e++) if (e != j0 && s[e] < u1) { u1 = s[e]; j1 = e; }

        float et  = expf(v1 - v0);
        float wt0 = 1.f / (1.f + et);
        float wt1 = et * wt0;
        float eb  = expf(u0 - u1);
        float wb1 = 1.f / (1.f + eb);
        float wb0 = eb * wb1;

        int p;
        p = atomicAdd(&g_cnt[i0], 1);
        g_pairTok[i0 * TOK + p] = gw;
        g_tokPair[gw * 4 + 0] = i0 * TOK + p;  g_tokW[gw * 4 + 0] = wt0;
        p = atomicAdd(&g_cnt[i1], 1);
        g_pairTok[i1 * TOK + p] = gw;
        g_tokPair[gw * 4 + 1] = i1 * TOK + p;  g_tokW[gw * 4 + 1] = wt1;
        p = atomicAdd(&g_cnt[j0], 1);
        g_pairTok[j0 * TOK + p] = gw;
        g_tokPair[gw * 4 + 2] = j0 * TOK + p;  g_tokW[gw * 4 + 2] = wb0;
        p = atomicAdd(&g_cnt[j1], 1);
        g_pairTok[j1 * TOK + p] = gw;
        g_tokPair[gw * 4 + 3] = j1 * TOK + p;  g_tokW[gw * 4 + 3] = wb1;
    }
}

// ---------------------------------------------------------------------------
// 1b) weight prep (merged W1+W2): W[e][k][n] fp32 -> Wt[e][n][k] fp16
// ---------------------------------------------------------------------------
__global__ void wconv_kernel(const float* __restrict__ W1,
                             const float* __restrict__ W2) {
    __shared__ float t[32][33];
    int z = blockIdx.z;
    int e = z & 7;
    int which = z >> 3;
    const float* W = which ? W2 : W1;
    __half* T = which ? g_w2t : g_w1t;
    int kb = blockIdx.x * 32, nb = blockIdx.y * 32;
    const float* src = W + (size_t)e * DDIM * DDIM;
    int tx = threadIdx.x, ty = threadIdx.y;
#pragma unroll
    for (int r = ty; r < 32; r += 8)
        t[r][tx] = src[(size_t)(kb + r) * DDIM + nb + tx];
    __syncthreads();
#pragma unroll
    for (int r = ty; r < 32; r += 8) {
        float v = t[tx][r];  // = W[kb+tx][nb+r]
        T[((size_t)e * DDIM + (nb + r)) * DDIM + kb + tx] = __float2half_rn(v);
    }
}

// ---------------------------------------------------------------------------
// 2) FUSED expert kernel: GEMM1 + LN1 + ReLU (smem) + GEMM2 + LN2 -> g_h2
//    BM=64 full rows, BN=512, BK=64, 512 threads, 16 warps (2 x 8),
//    warp tile 32x64, 2-stage cp.async per phase.
// ---------------------------------------------------------------------------
__global__ void __launch_bounds__(512, 1) expert_fused(
    const float* __restrict__ b1, const float* __restrict__ ln1w,
    const float* __restrict__ ln1b,
    const float* __restrict__ b2, const float* __restrict__ ln2w,
    const float* __restrict__ ln2b)
{
    const int e   = blockIdx.z;
    const int cnt = g_cnt[e];
    const int m0  = blockIdx.y * BM;
    if (m0 >= cnt) return;

    extern __shared__ char dsm[];
    const uint32_t sbase = smem_u32(dsm);
    __shared__ float red_s[BM][8];
    __shared__ float red_q[BM][8];
    __shared__ float sb_b[DDIM], sb_w[DDIM], sb_bb[DDIM];

    const int tid  = threadIdx.x;
    const int wid  = tid >> 5;
    const int lane = tid & 31;

    // loader bases: thread -> (row = tid>>3 in [0,64), seg ks = tid&7)
    const int lrow = tid >> 3;
    const int lks  = tid & 7;
    int rr = m0 + lrow; if (rr > cnt - 1) rr = cnt - 1;
    const int tokid = g_pairTok[e * TOK + rr];
    const __half* asrc = g_xh + (size_t)tokid * DDIM + lks * 8;
    const uint32_t adst = lrow * ROWB + lks * 16;
    const __half* b1src = g_w1t + ((size_t)e * DDIM + lrow) * DDIM + lks * 8;
    const __half* b2src = g_w2t + ((size_t)e * DDIM + lrow) * DDIM + lks * 8;
    const uint32_t bdst = P1_B_OFF + lrow * ROWB + lks * 16;  // phase1 B dst

    // warp layout: warp_m = wid>>3 (32 rows), warp_n = wid&7 (64 cols)
    const int warp_m = wid >> 3;
    const int warp_n = wid & 7;
    const int l15 = lane & 15;
    const uint32_t aoff  = (uint32_t)((warp_m * 32 + l15) * ROWB + (lane >> 4) * 16);
    const uint32_t boff  = (uint32_t)((warp_n * 64 + (lane >> 4) * 8 + (lane & 7)) * ROWB +
                                      ((lane >> 3) & 1) * 16);
    const uint32_t a2off = (uint32_t)((warp_m * 32 + l15) * A2_ROWB + (lane >> 4) * 16);

    const int group = lane >> 2;
    const int t4    = lane & 3;

    float acc[2][8][4];
#pragma unroll
    for (int mt = 0; mt < 2; mt++)
#pragma unroll
        for (int nt = 0; nt < 8; nt++)
#pragma unroll
            for (int q = 0; q < 4; q++) acc[mt][nt][q] = 0.f;

    // ======================= PHASE 1: h = x @ W1 ==========================
    auto issue1 = [&](int chunk, int s) {
        const int k0 = chunk * BK;
        const uint32_t sb = sbase + s * P1_STAGE;
        cp16(sb + adst, asrc + k0);
#pragma unroll
        for (int j = 0; j < 8; j++)
            cp16(sb + bdst + j * 9216, b1src + k0 + (size_t)j * 64 * DDIM);
    };

    issue1(0, 0); CP_COMMIT();
    for (int i = 0; i < NCHUNK; i++) {
        if (i + 1 < NCHUNK) issue1(i + 1, (i + 1) & 1);
        CP_COMMIT();
        if (i + 1 < NCHUNK) { CP_WAIT1(); } else { CP_WAIT0(); }
        __syncthreads();

        const uint32_t sb = sbase + (i & 1) * P1_STAGE;
        const uint32_t aA = sb + aoff;
        const uint32_t bB = sb + P1_B_OFF + boff;   // FIX: B region offset
#pragma unroll
        for (int k16 = 0; k16 < 4; k16++) {
            uint32_t bh[8][2];
#pragma unroll
            for (int p = 0; p < 4; p++) {
                uint32_t r4[4];
                ldsm4(r4, bB + p * 16 * ROWB + k16 * 32);
                bh[2 * p][0] = r4[0]; bh[2 * p][1] = r4[1];
                bh[2 * p + 1][0] = r4[2]; bh[2 * p + 1][1] = r4[3];
            }
#pragma unroll
            for (int mt = 0; mt < 2; mt++) {
                uint32_t ah[4];
                ldsm4(ah, aA + mt * 16 * ROWB + k16 * 32);
#pragma unroll
                for (int nt = 0; nt < 8; nt++)
                    mma16816(acc[mt][nt], ah, bh[nt]);
            }
        }
        __syncthreads();
    }

    // ---------------- epilogue 1: bias + LN1 + relu -> A2 (smem) -----------
    sb_b[tid]  = b1[(size_t)e * DDIM + tid];
    sb_w[tid]  = ln1w[(size_t)e * DDIM + tid];
    sb_bb[tid] = ln1b[(size_t)e * DDIM + tid];
    __syncthreads();

#pragma unroll
    for (int mt = 0; mt < 2; mt++) {
#pragma unroll
        for (int nt = 0; nt < 8; nt++) {
            int col = warp_n * 64 + nt * 8 + t4 * 2;
            float c0 = sb_b[col], c1 = sb_b[col + 1];
            acc[mt][nt][0] += c0; acc[mt][nt][1] += c1;
            acc[mt][nt][2] += c0; acc[mt][nt][3] += c1;
        }
        float s0 = 0.f, q0 = 0.f, s1 = 0.f, q1 = 0.f;
#pragma unroll
        for (int nt = 0; nt < 8; nt++) {
            s0 += acc[mt][nt][0] + acc[mt][nt][1];
            q0 += acc[mt][nt][0] * acc[mt][nt][0] + acc[mt][nt][1] * acc[mt][nt][1];
            s1 += acc[mt][nt][2] + acc[mt][nt][3];
            q1 += acc[mt][nt][2] * acc[mt][nt][2] + acc[mt][nt][3] * acc[mt][nt][3];
        }
#pragma unroll
        for (int o = 1; o <= 2; o <<= 1) {
            s0 += __shfl_xor_sync(0xffffffffu, s0, o);
            q0 += __shfl_xor_sync(0xffffffffu, q0, o);
            s1 += __shfl_xor_sync(0xffffffffu, s1, o);
            q1 += __shfl_xor_sync(0xffffffffu, q1, o);
        }
        if (t4 == 0) {
            int r0 = warp_m * 32 + mt * 16 + group;
            red_s[r0][warp_n] = s0;     red_q[r0][warp_n] = q0;
            red_s[r0 + 8][warp_n] = s1; red_q[r0 + 8][warp_n] = q1;
        }
    }
    __syncthreads();

#pragma unroll
    for (int mt = 0; mt < 2; mt++) {
#pragma unroll
        for (int h = 0; h < 2; h++) {
            int rloc = warp_m * 32 + mt * 16 + h * 8 + group;
            float ss = 0.f, qq = 0.f;
#pragma unroll
            for (int j = 0; j < 8; j++) { ss += red_s[rloc][j]; qq += red_q[rloc][j]; }
            float mu = ss * (1.f / DDIM);
            float var = qq * (1.f / DDIM) - mu * mu;
            float rstd = rsqrtf(var + LN_EPS);
            uint32_t arow = sbase + rloc * A2_ROWB;
#pragma unroll
            for (int nt = 0; nt < 8; nt++) {
                int col = warp_n * 64 + nt * 8 + t4 * 2;
                float y0 = fmaxf((acc[mt][nt][2 * h + 0] - mu) * rstd * sb_w[col] + sb_bb[col], 0.f);
                float y1 = fmaxf((acc[mt][nt][2 * h + 1] - mu) * rstd * sb_w[col + 1] + sb_bb[col + 1], 0.f);
                __half2 hv = __floats2half2_rn(y0, y1);
                asm volatile("st.shared.b32 [%0], %1;" :: "r"(arow + col * 2),
                             "r"(*(uint32_t*)&hv) : "memory");
            }
        }
    }

    // re-zero accumulators
#pragma unroll
    for (int mt = 0; mt < 2; mt++)
#pragma unroll
        for (int nt = 0; nt < 8; nt++)
#pragma unroll
            for (int q = 0; q < 4; q++) acc[mt][nt][q] = 0.f;
    __syncthreads();   // A2 ready

    // ======================= PHASE 2: h2 = A2 @ W2 =========================
    auto issue2 = [&](int chunk, int s) {
        const int k0 = chunk * BK;
        const uint32_t sb = sbase + P2_BASE + s * P2_STAGE;
#pragma unroll
        for (int j = 0; j < 8; j++)
            cp16(sb + (bdst - P1_B_OFF) + j * 9216, b2src + k0 + (size_t)j * 64 * DDIM);
    };

    issue2(0, 0); CP_COMMIT();
    for (int i = 0; i < NCHUNK; i++) {
        if (i + 1 < NCHUNK) issue2(i + 1, (i + 1) & 1);
        CP_COMMIT();
        if (i + 1 < NCHUNK) { CP_WAIT1(); } else { CP_WAIT0(); }
        __syncthreads();

        const uint32_t bB = sbase + P2_BASE + (i & 1) * P2_STAGE + boff;
        const uint32_t aA = sbase + a2off + i * (BK * 2);
#pragma unroll
        for (int k16 = 0; k16 < 4; k16++) {
            uint32_t bh[8][2];
#pragma unroll
            for (int p = 0; p < 4; p++) {
                uint32_t r4[4];
                ldsm4(r4, bB + p * 16 * ROWB + k16 * 32);
                bh[2 * p][0] = r4[0]; bh[2 * p][1] = r4[1];
                bh[2 * p + 1][0] = r4[2]; bh[2 * p + 1][1] = r4[3];
            }
#pragma unroll
            for (int mt = 0; mt < 2; mt++) {
                uint32_t ah[4];
                ldsm4(ah, aA + mt * 16 * A2_ROWB + k16 * 32);
#pragma unroll
                for (int nt = 0; nt < 8; nt++)
                    mma16816(acc[mt][nt], ah, bh[nt]);
            }
        }
        __syncthreads();
    }

    // ---------------- epilogue 2: bias + LN2 -> g_h2 (post-LN fp16) --------
    sb_b[tid]  = b2[(size_t)e * DDIM + tid];
    sb_w[tid]  = ln2w[(size_t)e * DDIM + tid];
    sb_bb[tid] = ln2b[(size_t)e * DDIM + tid];
    __syncthreads();

#pragma unroll
    for (int mt = 0; mt < 2; mt++) {
#pragma unroll
        for (int nt = 0; nt < 8; nt++) {
            int col = warp_n * 64 + nt * 8 + t4 * 2;
            float c0 = sb_b[col], c1 = sb_b[col + 1];
            acc[mt][nt][0] += c0; acc[mt][nt][1] += c1;
            acc[mt][nt][2] += c0; acc[mt][nt][3] += c1;
        }
        float s0 = 0.f, q0 = 0.f, s1 = 0.f, q1 = 0.f;
#pragma unroll
        for (int nt = 0; nt < 8; nt++) {
            s0 += acc[mt][nt][0] + acc[mt][nt][1];
            q0 += acc[mt][nt][0] * acc[mt][nt][0] + acc[mt][nt][1] * acc[mt][nt][1];
            s1 += acc[mt][nt][2] + acc[mt][nt][3];
            q1 += acc[mt][nt][2] * acc[mt][nt][2] + acc[mt][nt][3] * acc[mt][nt][3];
        }
#pragma unroll
        for (int o = 1; o <= 2; o <<= 1) {
            s0 += __shfl_xor_sync(0xffffffffu, s0, o);
            q0 += __shfl_xor_sync(0xffffffffu, q0, o);
            s1 += __shfl_xor_sync(0xffffffffu, s1, o);
            q1 += __shfl_xor_sync(0xffffffffu, q1, o);
        }
        if (t4 == 0) {
            int r0 = warp_m * 32 + mt * 16 + group;
            red_s[r0][warp_n] = s0;     red_q[r0][warp_n] = q0;
            red_s[r0 + 8][warp_n] = s1; red_q[r0 + 8][warp_n] = q1;
        }
    }
    __syncthreads();

#pragma unroll
    for (int mt = 0; mt < 2; mt++) {
#pragma unroll
        for (int h = 0; h < 2; h++) {
            int rloc = warp_m * 32 + mt * 16 + h * 8 + group;
            int r = m0 + rloc;
            if (r >= cnt) continue;
            float ss = 0.f, qq = 0.f;
#pragma unroll
            for (int j = 0; j < 8; j++) { ss += red_s[rloc][j]; qq += red_q[rloc][j]; }
            float mu = ss * (1.f / DDIM);
            float var = qq * (1.f / DDIM) - mu * mu;
            float rstd = rsqrtf(var + LN_EPS);
            __half* orow = g_h2 + ((size_t)e * TOK + r) * DDIM;
#pragma unroll
            for (int nt = 0; nt < 8; nt++) {
                int col = warp_n * 64 + nt * 8 + t4 * 2;
                float y0 = (acc[mt][nt][2 * h + 0] - mu) * rstd * sb_w[col] + sb_bb[col];
                float y1 = (acc[mt][nt][2 * h + 1] - mu) * rstd * sb_w[col + 1] + sb_bb[col + 1];
                *(__half2*)(orow + col) = __floats2half2_rn(y0, y1);
            }
        }
    }
}

// ---------------------------------------------------------------------------
// 6) combine: warp per token; 4 post-LN fp16 rows of g_h2, weighted sums
// ---------------------------------------------------------------------------
__global__ void combine_kernel(const float* __restrict__ x,
                               float* __restrict__ out) {
    int gw   = (blockIdx.x * blockDim.x + threadIdx.x) >> 5;
    int lane = threadIdx.x & 31;
    const int t = gw;

    int   pr[4];
    float wt[4];
#pragma unroll
    for (int j = 0; j < 4; j++) {
        pr[j] = g_tokPair[t * 4 + j];
        wt[j] = g_tokW[t * 4 + j];
    }

    const __half2* ra = (const __half2*)(g_h2 + (size_t)pr[0] * DDIM);
    const __half2* rb = (const __half2*)(g_h2 + (size_t)pr[1] * DDIM);
    const __half2* rc = (const __half2*)(g_h2 + (size_t)pr[2] * DDIM);
    const __half2* rd = (const __half2*)(g_h2 + (size_t)pr[3] * DDIM);
    const float* xr = x + (size_t)t * DDIM;
    float* o_out = out + (size_t)t * DDIM;
    float* o_top = out + (size_t)BND + (size_t)t * DDIM;
    float* o_bot = out + 2 * (size_t)BND + (size_t)t * DDIM;

    float accd = 0.f;
#pragma unroll
    for (int i = 0; i < 8; i++) {
        int c = lane + i * 32;
        float2 va = __half22float2(ra[c]);
        float2 vb = __half22float2(rb[c]);
        float2 vc = __half22float2(rc[c]);
        float2 vd = __half22float2(rd[c]);
        float topx = wt[0] * va.x + wt[1] * vb.x;
        float topy = wt[0] * va.y + wt[1] * vb.y;
        float botx = wt[2] * vc.x + wt[3] * vd.x;
        float boty = wt[2] * vc.y + wt[3] * vd.y;
        int d = 2 * c;
        o_top[d] = topx;     o_top[d + 1] = topy;
        o_bot[d] = botx;     o_bot[d + 1] = boty;
        o_out[d] = topx + xr[d];
        o_out[d + 1] = topy + xr[d + 1];
        float dfx = topx - botx, dfy = topy - boty;
        accd += dfx * dfx + dfy * dfy;
    }
#pragma unroll
    for (int o = 16; o > 0; o >>= 1) accd += __shfl_xor_sync(0xffffffffu, accd, o);

    __shared__ float red[8];
    if (lane == 0) red[threadIdx.x >> 5] = accd;
    __syncthreads();
    if (threadIdx.x == 0) {
        float ssum = 0.f;
        for (int i = 0; i < 8; i++) ssum += red[i];
        g_part[blockIdx.x] = ssum;
    }
}

// ---------------------------------------------------------------------------
// 7) loss
// ---------------------------------------------------------------------------
__global__ void loss_kernel(float* __restrict__ out) {
    int w = threadIdx.x >> 5, lane = threadIdx.x & 31;
    __shared__ float lred[8];
    float s = 0.f;
    for (int i = lane; i < 512; i += 32) s += g_part[w * 512 + i];
#pragma unroll
    for (int o = 16; o > 0; o >>= 1) s += __shfl_xor_sync(0xffffffffu, s, o);
    if (lane == 0) lred[w] = 1.f / (sqrtf(s) + 1e-8f);
    __syncthreads();
    if (threadIdx.x == 0) {
        float a = 0.f;
        for (int i = 0; i < 8; i++) a += lred[i];
        out[(size_t)3 * BND] = a * (1.f / 8.f);
    }
}

// ---------------------------------------------------------------------------
// launch
// ---------------------------------------------------------------------------
extern "C" void kernel_launch(void* const* d_in, const int* in_sizes, int n_in,
                              void* d_out, int out_size) {
    const float* x    = (const float*)d_in[0];
    const float* Wg   = (const float*)d_in[1];
    const float* bg   = (const float*)d_in[2];
    const float* W1   = (const float*)d_in[3];
    const float* b1   = (const float*)d_in[4];
    const float* ln1w = (const float*)d_in[5];
    const float* ln1b = (const float*)d_in[6];
    const float* W2   = (const float*)d_in[7];
    const float* b2   = (const float*)d_in[8];
    const float* ln2w = (const float*)d_in[9];
    const float* ln2b = (const float*)d_in[10];
    float* out = (float*)d_out;

    static int smem_set = 0;
    if (!smem_set) {
        cudaFuncSetAttribute(expert_fused, cudaFuncAttributeMaxDynamicSharedMemorySize, SMEM_DYN);
        smem_set = 1;
    }

    init_kernel<<<1, 32>>>();
    gating_kernel<<<TOK * 32 / 256, 256>>>(x, Wg, bg);

    dim3 wgrid(DDIM / 32, DDIM / 32, 2 * NEXP);   // merged W1+W2
    wconv_kernel<<<wgrid, dim3(32, 8)>>>(W1, W2);

    dim3 ggrid(1, TOK / BM, NEXP);   // (1, 512, 8); ~half exit early
    expert_fused<<<ggrid, 512, SMEM_DYN>>>(b1, ln1w, ln1b, b2, ln2w, ln2b);

    combine_kernel<<<TOK * 32 / 256, 256>>>(x, out);
    loss_kernel<<<1, 256>>>(out);
}

// round 15
// speedup vs baseline: 1.1345x; 1.1345x over previous
#include <cuda_runtime.h>
#include <cuda_fp16.h>
#include <math.h>
#include <stdint.h>

// Problem constants
#define TOK   32768          // B*N = 8*4096
#define NEXP  8
#define DDIM  512
#define BND   16777216       // TOK * DDIM
#define LN_EPS 1e-5f

// Fused config: BM=64, BN=512, BK=64, 512 threads, swizzled 128B rows
#define BM 64
#define BN 512
#define BK 64
#define NCHUNK (DDIM / BK)            // 8
#define P1_B 8192                     // B offset within phase-1 stage
#define P1_STAGE 73728                // 8192 (A) + 65536 (B), low-10-bits aligned
#define A2_ROWB 1040                  // 512 fp16 + 16B pad (linear, conflict-free)
#define A2_SIZE (BM * A2_ROWB)        // 66560
#define P2_BASE A2_SIZE               // 66560 (1024-aligned)
#define P2_STAGE 65536
#define SMEM_DYN (3 * P1_STAGE)       // 221184 (covers P2_BASE + 2*P2_STAGE = 197632)

// ---------------------------------------------------------------------------
// Scratch (__device__ globals; no allocations allowed)
// ---------------------------------------------------------------------------
__device__ int   g_cnt[NEXP];
__device__ int   g_pairTok[NEXP * TOK];
__device__ int   g_tokPair[TOK * 4];
__device__ float g_tokW[TOK * 4];
__device__ __half g_h2[(size_t)NEXP * TOK * DDIM];   // expert out (POST-LN2) fp16
__device__ float g_part[4096];
__device__ __half g_xh[(size_t)TOK * DDIM];          // x fp16 (token space)
__device__ __half g_w1t[(size_t)NEXP * DDIM * DDIM]; // W1^T fp16
__device__ __half g_w2t[(size_t)NEXP * DDIM * DDIM]; // W2^T fp16

// ---------------------------------------------------------------------------
// Helpers
// ---------------------------------------------------------------------------
__device__ __forceinline__ uint32_t smem_u32(const void* p) {
    uint32_t a;
    asm("{ .reg .u64 t; cvta.to.shared.u64 t, %1; cvt.u32.u64 %0, t; }" : "=r"(a) : "l"(p));
    return a;
}
__device__ __forceinline__ void cp16(uint32_t dst, const void* src) {
    asm volatile("cp.async.cg.shared.global [%0], [%1], 16;" :: "r"(dst), "l"(src));
}
#define CP_COMMIT() asm volatile("cp.async.commit_group;" ::: "memory")
#define CP_WAIT1()  asm volatile("cp.async.wait_group 1;" ::: "memory")
__device__ __forceinline__ void ldsm4(uint32_t* r, uint32_t addr) {
    asm volatile("ldmatrix.sync.aligned.m8n8.x4.shared.b16 {%0,%1,%2,%3}, [%4];"
                 : "=r"(r[0]), "=r"(r[1]), "=r"(r[2]), "=r"(r[3]) : "r"(addr));
}
__device__ __forceinline__ void mma16816(float* c, const uint32_t* a, const uint32_t* b) {
    asm volatile(
        "mma.sync.aligned.m16n8k16.row.col.f32.f16.f16.f32 "
        "{%0,%1,%2,%3}, {%4,%5,%6,%7}, {%8,%9}, {%0,%1,%2,%3};"
        : "+f"(c[0]), "+f"(c[1]), "+f"(c[2]), "+f"(c[3])
        : "r"(a[0]), "r"(a[1]), "r"(a[2]), "r"(a[3]), "r"(b[0]), "r"(b[1]));
}

// ---------------------------------------------------------------------------
// 0) zero counters
// ---------------------------------------------------------------------------
__global__ void init_kernel() {
    if (threadIdx.x < NEXP) g_cnt[threadIdx.x] = 0;
}

// ---------------------------------------------------------------------------
// 1) gating: scores + routing + x fp16 round (token space)
// ---------------------------------------------------------------------------
__global__ void gating_kernel(const float* __restrict__ x,
                              const float* __restrict__ Wg,
                              const float* __restrict__ bg) {
    int gw = (blockIdx.x * blockDim.x + threadIdx.x) >> 5;
    if (gw >= TOK) return;
    int lane = threadIdx.x & 31;
    const float* xr = x + (size_t)gw * DDIM;
    __half* xh = g_xh + (size_t)gw * DDIM;

    float s[NEXP];
#pragma unroll
    for (int e = 0; e < NEXP; e++) s[e] = 0.f;
#pragma unroll
    for (int i = 0; i < 16; i++) {
        int d = lane + i * 32;
        float xv = xr[d];
        const float* wr = Wg + d * NEXP;
#pragma unroll
        for (int e = 0; e < NEXP; e++) s[e] += xv * wr[e];
        xh[d] = __float2half_rn(xv);
    }
#pragma unroll
    for (int e = 0; e < NEXP; e++) {
#pragma unroll
        for (int o = 16; o > 0; o >>= 1)
            s[e] += __shfl_xor_sync(0xffffffffu, s[e], o);
    }
    if (lane == 0) {
#pragma unroll
        for (int e = 0; e < NEXP; e++) s[e] += bg[e];
        int i0 = 0; float v0 = s[0];
        for (int e = 1; e < NEXP; e++) if (s[e] > v0) { v0 = s[e]; i0 = e; }
        int i1 = -1; float v1 = -1e30f;
        for (int e = 0; e < NEXP; e++) if (e != i0 && s[e] > v1) { v1 = s[e]; i1 = e; }
        int j0 = 0; float u0 = s[0];
        for (int e = 1; e < NEXP; e++) if (s[e] < u0) { u0 = s[e]; j0 = e; }
        int j1 = -1; float u1 = 1e30f;
        for (int e = 0; e < NEXP; e++) if (e != j0 && s[e] < u1) { u1 = s[e]; j1 = e; }

        float et  = expf(v1 - v0);
        float wt0 = 1.f / (1.f + et);
        float wt1 = et * wt0;
        float eb  = expf(u0 - u1);
        float wb1 = 1.f / (1.f + eb);
        float wb0 = eb * wb1;

        int p;
        p = atomicAdd(&g_cnt[i0], 1);
        g_pairTok[i0 * TOK + p] = gw;
        g_tokPair[gw * 4 + 0] = i0 * TOK + p;  g_tokW[gw * 4 + 0] = wt0;
        p = atomicAdd(&g_cnt[i1], 1);
        g_pairTok[i1 * TOK + p] = gw;
        g_tokPair[gw * 4 + 1] = i1 * TOK + p;  g_tokW[gw * 4 + 1] = wt1;
        p = atomicAdd(&g_cnt[j0], 1);
        g_pairTok[j0 * TOK + p] = gw;
        g_tokPair[gw * 4 + 2] = j0 * TOK + p;  g_tokW[gw * 4 + 2] = wb0;
        p = atomicAdd(&g_cnt[j1], 1);
        g_pairTok[j1 * TOK + p] = gw;
        g_tokPair[gw * 4 + 3] = j1 * TOK + p;  g_tokW[gw * 4 + 3] = wb1;
    }
}

// ---------------------------------------------------------------------------
// 1b) weight prep (merged W1+W2): W[e][k][n] fp32 -> Wt[e][n][k] fp16
// ---------------------------------------------------------------------------
__global__ void wconv_kernel(const float* __restrict__ W1,
                             const float* __restrict__ W2) {
    __shared__ float t[32][33];
    int z = blockIdx.z;
    int e = z & 7;
    int which = z >> 3;
    const float* W = which ? W2 : W1;
    __half* T = which ? g_w2t : g_w1t;
    int kb = blockIdx.x * 32, nb = blockIdx.y * 32;
    const float* src = W + (size_t)e * DDIM * DDIM;
    int tx = threadIdx.x, ty = threadIdx.y;
#pragma unroll
    for (int r = ty; r < 32; r += 8)
        t[r][tx] = src[(size_t)(kb + r) * DDIM + nb + tx];
    __syncthreads();
#pragma unroll
    for (int r = ty; r < 32; r += 8) {
        float v = t[tx][r];  // = W[kb+tx][nb+r]
        T[((size_t)e * DDIM + (nb + r)) * DDIM + kb + tx] = __float2half_rn(v);
    }
}

// ---------------------------------------------------------------------------
// 2) FUSED expert kernel: GEMM1 + LN1 + ReLU (smem) + GEMM2 + LN2 -> g_h2
//    Swizzled 128B stages; phase1 3-stage / 1 sync per chunk; phase2 2-stage
//    with cross-phase prefetch. 512 threads, 16 warps (2 x 8), warp 32x64.
// ---------------------------------------------------------------------------
__global__ void __launch_bounds__(512, 1) expert_fused(
    const float* __restrict__ b1, const float* __restrict__ ln1w,
    const float* __restrict__ ln1b,
    const float* __restrict__ b2, const float* __restrict__ ln2w,
    const float* __restrict__ ln2b)
{
    const int e   = blockIdx.z;
    const int cnt = g_cnt[e];
    const int m0  = blockIdx.y * BM;
    if (m0 >= cnt) return;

    extern __shared__ char dsm[];
    const uint32_t sbase = smem_u32(dsm);
    __shared__ float red_s[BM][8];
    __shared__ float red_q[BM][8];
    __shared__ float sb_b[DDIM], sb_w[DDIM], sb_bb[DDIM];

    const int tid  = threadIdx.x;
    const int wid  = tid >> 5;
    const int lane = tid & 31;

    // loader: row = tid>>3 in [0,64), seg = tid&7; swizzled dst
    const int lrow = tid >> 3;
    const int lks  = tid & 7;
    const uint32_t lsw = (uint32_t)(lrow * 128 + ((lks ^ (lrow & 7)) * 16));
    int rr = m0 + lrow; if (rr > cnt - 1) rr = cnt - 1;
    const int tokid = g_pairTok[e * TOK + rr];
    const __half* asrc  = g_xh + (size_t)tokid * DDIM + lks * 8;
    const __half* b1src = g_w1t + ((size_t)e * DDIM + lrow) * DDIM + lks * 8;
    const __half* b2src = g_w2t + ((size_t)e * DDIM + lrow) * DDIM + lks * 8;

    // warp layout: warp_m = wid>>3 (32 rows), warp_n = wid&7 (64 cols)
    const int warp_m = wid >> 3;
    const int warp_n = wid & 7;
    const int l15 = lane & 15;
    // fragment swizzle constants
    const uint32_t XA  = (uint32_t)((l15 & 7) << 4);
    const uint32_t c0A = (uint32_t)((lane >> 4) * 16);
    const uint32_t XB  = (uint32_t)((lane & 7) << 4);
    const uint32_t c0B = (uint32_t)(((lane >> 3) & 1) * 16);
    const uint32_t aRow = (uint32_t)((warp_m * 32 + l15) * 128);
    const uint32_t bRow = (uint32_t)((warp_n * 64 + (lane >> 4) * 8 + (lane & 7)) * 128);
    const uint32_t a2off = (uint32_t)((warp_m * 32 + l15) * A2_ROWB + (lane >> 4) * 16);

    const int group = lane >> 2;
    const int t4    = lane & 3;

    float acc[2][8][4];
#pragma unroll
    for (int mt = 0; mt < 2; mt++)
#pragma unroll
        for (int nt = 0; nt < 8; nt++)
#pragma unroll
            for (int q = 0; q < 4; q++) acc[mt][nt][q] = 0.f;

    // ======================= PHASE 1: h = x @ W1 (3-stage) =================
    auto issue1 = [&](int chunk, int s) {
        const int k0 = chunk * BK;
        const uint32_t sb = sbase + s * P1_STAGE;
        cp16(sb + lsw, asrc + k0);
#pragma unroll
        for (int j = 0; j < 8; j++)
            cp16(sb + P1_B + j * 8192 + lsw, b1src + k0 + (size_t)j * 64 * DDIM);
    };

    issue1(0, 0); CP_COMMIT();
    issue1(1, 1); CP_COMMIT();
    for (int i = 0; i < NCHUNK; i++) {
        CP_WAIT1();
        __syncthreads();
        if (i + 2 < NCHUNK) issue1(i + 2, (i + 2) % 3);
        CP_COMMIT();

        const uint32_t sb = sbase + (i % 3) * P1_STAGE;
#pragma unroll
        for (int k16 = 0; k16 < 4; k16++) {
            const uint32_t cB = (c0B + 32 * k16) ^ XB;
            const uint32_t cA = (c0A + 32 * k16) ^ XA;
            uint32_t bh[8][2];
#pragma unroll
            for (int p = 0; p < 4; p++) {
                uint32_t r4[4];
                ldsm4(r4, sb + P1_B + bRow + p * 2048 + cB);
                bh[2 * p][0] = r4[0]; bh[2 * p][1] = r4[1];
                bh[2 * p + 1][0] = r4[2]; bh[2 * p + 1][1] = r4[3];
            }
#pragma unroll
            for (int mt = 0; mt < 2; mt++) {
                uint32_t ah[4];
                ldsm4(ah, sb + aRow + mt * 2048 + cA);
#pragma unroll
                for (int nt = 0; nt < 8; nt++)
                    mma16816(acc[mt][nt], ah, bh[nt]);
            }
        }
    }
    __syncthreads();   // phase-1 stages dead; safe to reuse for P2 / A2

    // cross-phase prefetch: phase-2 B chunks 0,1 overlap epilogue 1
    auto issue2 = [&](int chunk, int s) {
        const int k0 = chunk * BK;
        const uint32_t sb = sbase + P2_BASE + s * P2_STAGE;
#pragma unroll
        for (int j = 0; j < 8; j++)
            cp16(sb + j * 8192 + lsw, b2src + k0 + (size_t)j * 64 * DDIM);
    };
    issue2(0, 0); CP_COMMIT();
    issue2(1, 1); CP_COMMIT();

    // ---------------- epilogue 1: bias + LN1 + relu -> A2 (smem) -----------
    sb_b[tid]  = b1[(size_t)e * DDIM + tid];
    sb_w[tid]  = ln1w[(size_t)e * DDIM + tid];
    sb_bb[tid] = ln1b[(size_t)e * DDIM + tid];
    __syncthreads();

#pragma unroll
    for (int mt = 0; mt < 2; mt++) {
#pragma unroll
        for (int nt = 0; nt < 8; nt++) {
            int col = warp_n * 64 + nt * 8 + t4 * 2;
            float c0 = sb_b[col], c1 = sb_b[col + 1];
            acc[mt][nt][0] += c0; acc[mt][nt][1] += c1;
            acc[mt][nt][2] += c0; acc[mt][nt][3] += c1;
        }
        float s0 = 0.f, q0 = 0.f, s1 = 0.f, q1 = 0.f;
#pragma unroll
        for (int nt = 0; nt < 8; nt++) {
            s0 += acc[mt][nt][0] + acc[mt][nt][1];
            q0 += acc[mt][nt][0] * acc[mt][nt][0] + acc[mt][nt][1] * acc[mt][nt][1];
            s1 += acc[mt][nt][2] + acc[mt][nt][3];
            q1 += acc[mt][nt][2] * acc[mt][nt][2] + acc[mt][nt][3] * acc[mt][nt][3];
        }
#pragma unroll
        for (int o = 1; o <= 2; o <<= 1) {
            s0 += __shfl_xor_sync(0xffffffffu, s0, o);
            q0 += __shfl_xor_sync(0xffffffffu, q0, o);
            s1 += __shfl_xor_sync(0xffffffffu, s1, o);
            q1 += __shfl_xor_sync(0xffffffffu, q1, o);
        }
        if (t4 == 0) {
            int r0 = warp_m * 32 + mt * 16 + group;
            red_s[r0][warp_n] = s0;     red_q[r0][warp_n] = q0;
            red_s[r0 + 8][warp_n] = s1; red_q[r0 + 8][warp_n] = q1;
        }
    }
    __syncthreads();

#pragma unroll
    for (int mt = 0; mt < 2; mt++) {
#pragma unroll
        for (int h = 0; h < 2; h++) {
            int rloc = warp_m * 32 + mt * 16 + h * 8 + group;
            float ss = 0.f, qq = 0.f;
#pragma unroll
            for (int j = 0; j < 8; j++) { ss += red_s[rloc][j]; qq += red_q[rloc][j]; }
            float mu = ss * (1.f / DDIM);
            float var = qq * (1.f / DDIM) - mu * mu;
            float rstd = rsqrtf(var + LN_EPS);
            uint32_t arow = sbase + rloc * A2_ROWB;
#pragma unroll
            for (int nt = 0; nt < 8; nt++) {
                int col = warp_n * 64 + nt * 8 + t4 * 2;
                float y0 = fmaxf((acc[mt][nt][2 * h + 0] - mu) * rstd * sb_w[col] + sb_bb[col], 0.f);
                float y1 = fmaxf((acc[mt][nt][2 * h + 1] - mu) * rstd * sb_w[col + 1] + sb_bb[col + 1], 0.f);
                __half2 hv = __floats2half2_rn(y0, y1);
                asm volatile("st.shared.b32 [%0], %1;" :: "r"(arow + col * 2),
                             "r"(*(uint32_t*)&hv) : "memory");
            }
        }
    }

    // re-zero accumulators
#pragma unroll
    for (int mt = 0; mt < 2; mt++)
#pragma unroll
        for (int nt = 0; nt < 8; nt++)
#pragma unroll
            for (int q = 0; q < 4; q++) acc[mt][nt][q] = 0.f;
    __syncthreads();   // A2 ready

    // ======================= PHASE 2: h2 = A2 @ W2 (2-stage) ===============
    for (int i = 0; i < NCHUNK; i++) {
        CP_WAIT1();
        __syncthreads();

        const uint32_t sb = sbase + P2_BASE + (i & 1) * P2_STAGE;
        const uint32_t aA = sbase + a2off + i * (BK * 2);
#pragma unroll
        for (int k16 = 0; k16 < 4; k16++) {
            const uint32_t cB = (c0B + 32 * k16) ^ XB;
            uint32_t bh[8][2];
#pragma unroll
            for (int p = 0; p < 4; p++) {
                uint32_t r4[4];
                ldsm4(r4, sb + bRow + p * 2048 + cB);
                bh[2 * p][0] = r4[0]; bh[2 * p][1] = r4[1];
                bh[2 * p + 1][0] = r4[2]; bh[2 * p + 1][1] = r4[3];
            }
#pragma unroll
            for (int mt = 0; mt < 2; mt++) {
                uint32_t ah[4];
                ldsm4(ah, aA + mt * 16 * A2_ROWB + k16 * 32);
#pragma unroll
                for (int nt = 0; nt < 8; nt++)
                    mma16816(acc[mt][nt], ah, bh[nt]);
            }
        }
        __syncthreads();
        if (i + 2 < NCHUNK) issue2(i + 2, (i + 2) & 1);
        CP_COMMIT();
    }

    // ---------------- epilogue 2: bias + LN2 -> g_h2 (post-LN fp16) --------
    sb_b[tid]  = b2[(size_t)e * DDIM + tid];
    sb_w[tid]  = ln2w[(size_t)e * DDIM + tid];
    sb_bb[tid] = ln2b[(size_t)e * DDIM + tid];
    __syncthreads();

#pragma unroll
    for (int mt = 0; mt < 2; mt++) {
#pragma unroll
        for (int nt = 0; nt < 8; nt++) {
            int col = warp_n * 64 + nt * 8 + t4 * 2;
            float c0 = sb_b[col], c1 = sb_b[col + 1];
            acc[mt][nt][0] += c0; acc[mt][nt][1] += c1;
            acc[mt][nt][2] += c0; acc[mt][nt][3] += c1;
        }
        float s0 = 0.f, q0 = 0.f, s1 = 0.f, q1 = 0.f;
#pragma unroll
        for (int nt = 0; nt < 8; nt++) {
            s0 += acc[mt][nt][0] + acc[mt][nt][1];
            q0 += acc[mt][nt][0] * acc[mt][nt][0] + acc[mt][nt][1] * acc[mt][nt][1];
            s1 += acc[mt][nt][2] + acc[mt][nt][3];
            q1 += acc[mt][nt][2] * acc[mt][nt][2] + acc[mt][nt][3] * acc[mt][nt][3];
        }
#pragma unroll
        for (int o = 1; o <= 2; o <<= 1) {
            s0 += __shfl_xor_sync(0xffffffffu, s0, o);
            q0 += __shfl_xor_sync(0xffffffffu, q0, o);
            s1 += __shfl_xor_sync(0xffffffffu, s1, o);
            q1 += __shfl_xor_sync(0xffffffffu, q1, o);
        }
        if (t4 == 0) {
            int r0 = warp_m * 32 + mt * 16 + group;
            red_s[r0][warp_n] = s0;     red_q[r0][warp_n] = q0;
            red_s[r0 + 8][warp_n] = s1; red_q[r0 + 8][warp_n] = q1;
        }
    }
    __syncthreads();

#pragma unroll
    for (int mt = 0; mt < 2; mt++) {
#pragma unroll
        for (int h = 0; h < 2; h++) {
            int rloc = warp_m * 32 + mt * 16 + h * 8 + group;
            int r = m0 + rloc;
            if (r >= cnt) continue;
            float ss = 0.f, qq = 0.f;
#pragma unroll
            for (int j = 0; j < 8; j++) { ss += red_s[rloc][j]; qq += red_q[rloc][j]; }
            float mu = ss * (1.f / DDIM);
            float var = qq * (1.f / DDIM) - mu * mu;
            float rstd = rsqrtf(var + LN_EPS);
            __half* orow = g_h2 + ((size_t)e * TOK + r) * DDIM;
#pragma unroll
            for (int nt = 0; nt < 8; nt++) {
                int col = warp_n * 64 + nt * 8 + t4 * 2;
                float y0 = (acc[mt][nt][2 * h + 0] - mu) * rstd * sb_w[col] + sb_bb[col];
                float y1 = (acc[mt][nt][2 * h + 1] - mu) * rstd * sb_w[col + 1] + sb_bb[col + 1];
                *(__half2*)(orow + col) = __floats2half2_rn(y0, y1);
            }
        }
    }
}

// ---------------------------------------------------------------------------
// 6) combine: warp per token; 4 post-LN fp16 rows of g_h2, weighted sums
// ---------------------------------------------------------------------------
__global__ void combine_kernel(const float* __restrict__ x,
                               float* __restrict__ out) {
    int gw   = (blockIdx.x * blockDim.x + threadIdx.x) >> 5;
    int lane = threadIdx.x & 31;
    const int t = gw;

    int   pr[4];
    float wt[4];
#pragma unroll
    for (int j = 0; j < 4; j++) {
        pr[j] = g_tokPair[t * 4 + j];
        wt[j] = g_tokW[t * 4 + j];
    }

    const __half2* ra = (const __half2*)(g_h2 + (size_t)pr[0] * DDIM);
    const __half2* rb = (const __half2*)(g_h2 + (size_t)pr[1] * DDIM);
    const __half2* rc = (const __half2*)(g_h2 + (size_t)pr[2] * DDIM);
    const __half2* rd = (const __half2*)(g_h2 + (size_t)pr[3] * DDIM);
    const float* xr = x + (size_t)t * DDIM;
    float* o_out = out + (size_t)t * DDIM;
    float* o_top = out + (size_t)BND + (size_t)t * DDIM;
    float* o_bot = out + 2 * (size_t)BND + (size_t)t * DDIM;

    float accd = 0.f;
#pragma unroll
    for (int i = 0; i < 8; i++) {
        int c = lane + i * 32;
        float2 va = __half22float2(ra[c]);
        float2 vb = __half22float2(rb[c]);
        float2 vc = __half22float2(rc[c]);
        float2 vd = __half22float2(rd[c]);
        float topx = wt[0] * va.x + wt[1] * vb.x;
        float topy = wt[0] * va.y + wt[1] * vb.y;
        float botx = wt[2] * vc.x + wt[3] * vd.x;
        float boty = wt[2] * vc.y + wt[3] * vd.y;
        int d = 2 * c;
        o_top[d] = topx;     o_top[d + 1] = topy;
        o_bot[d] = botx;     o_bot[d + 1] = boty;
        o_out[d] = topx + xr[d];
        o_out[d + 1] = topy + xr[d + 1];
        float dfx = topx - botx, dfy = topy - boty;
        accd += dfx * dfx + dfy * dfy;
    }
#pragma unroll
    for (int o = 16; o > 0; o >>= 1) accd += __shfl_xor_sync(0xffffffffu, accd, o);

    __shared__ float red[8];
    if (lane == 0) red[threadIdx.x >> 5] = accd;
    __syncthreads();
    if (threadIdx.x == 0) {
        float ssum = 0.f;
        for (int i = 0; i < 8; i++) ssum += red[i];
        g_part[blockIdx.x] = ssum;
    }
}

// ---------------------------------------------------------------------------
// 7) loss
// ---------------------------------------------------------------------------
__global__ void loss_kernel(float* __restrict__ out) {
    int w = threadIdx.x >> 5, lane = threadIdx.x & 31;
    __shared__ float lred[8];
    float s = 0.f;
    for (int i = lane; i < 512; i += 32) s += g_part[w * 512 + i];
#pragma unroll
    for (int o = 16; o > 0; o >>= 1) s += __shfl_xor_sync(0xffffffffu, s, o);
    if (lane == 0) lred[w] = 1.f / (sqrtf(s) + 1e-8f);
    __syncthreads();
    if (threadIdx.x == 0) {
        float a = 0.f;
        for (int i = 0; i < 8; i++) a += lred[i];
        out[(size_t)3 * BND] = a * (1.f / 8.f);
    }
}

// ---------------------------------------------------------------------------
// launch
// ---------------------------------------------------------------------------
extern "C" void kernel_launch(void* const* d_in, const int* in_sizes, int n_in,
                              void* d_out, int out_size) {
    const float* x    = (const float*)d_in[0];
    const float* Wg   = (const float*)d_in[1];
    const float* bg   = (const float*)d_in[2];
    const float* W1   = (const float*)d_in[3];
    const float* b1   = (const float*)d_in[4];
    const float* ln1w = (const float*)d_in[5];
    const float* ln1b = (const float*)d_in[6];
    const float* W2   = (const float*)d_in[7];
    const float* b2   = (const float*)d_in[8];
    const float* ln2w = (const float*)d_in[9];
    const float* ln2b = (const float*)d_in[10];
    float* out = (float*)d_out;

    static int smem_set = 0;
    if (!smem_set) {
        cudaFuncSetAttribute(expert_fused, cudaFuncAttributeMaxDynamicSharedMemorySize, SMEM_DYN);
        smem_set = 1;
    }

    init_kernel<<<1, 32>>>();
    gating_kernel<<<TOK * 32 / 256, 256>>>(x, Wg, bg);

    dim3 wgrid(DDIM / 32, DDIM / 32, 2 * NEXP);   // merged W1+W2
    wconv_kernel<<<wgrid, dim3(32, 8)>>>(W1, W2);

    dim3 ggrid(1, TOK / BM, NEXP);   // (1, 512, 8); ~half exit early
    expert_fused<<<ggrid, 512, SMEM_DYN>>>(b1, ln1w, ln1b, b2, ln2w, ln2b);

    combine_kernel<<<TOK * 32 / 256, 256>>>(x, out);
    loss_kernel<<<1, 256>>>(out);
}